// round 4
// baseline (speedup 1.0000x reference)
#include <cuda_runtime.h>
#include <math.h>

#define B_ 64
#define T_ 512
#define I_ 128
#define H_ 256
#define G_ 1024   // 4*H
#define C_ 3

#define NGROUP 16   // batch groups
#define BPG 4       // batches per group
#define RPG 8       // CTAs per group
#define JPR 32      // j-values per CTA (H / RPG)

// ---------------- scratch (device globals; no allocation allowed) ----------
__device__ float d_G0[B_ * T_ * G_];     // gates_x layer 0   (134 MB)
__device__ float d_G1[B_ * T_ * G_];     // gates_x layer 1   (134 MB)
__device__ float d_H0[B_ * T_ * H_];     // h outputs layer 0 (33.5 MB)
__device__ float d_HL[B_ * H_];          // last h of layer 1
__device__ float d_hx[2][B_ * H_];       // h exchange, double buffered
__device__ int   d_bar[NGROUP];          // per-group step barrier (zero-init)
__device__ int   d_done[NGROUP];         // per-group exit counter (zero-init)

// ---------------------------------------------------------------------------
// GEMM (NT): C[m][n] = sum_k A[m*K+k] * Bw[n*K+k] + bias1[n] + bias2[n]
// BM=BN=128, BK=8, 256 threads, 8x8 per thread. M,N,K all divisible.
// ---------------------------------------------------------------------------
__global__ void __launch_bounds__(256) gemm_nt_bias(
    const float* __restrict__ A, const float* __restrict__ Bw,
    const float* __restrict__ bias1, const float* __restrict__ bias2,
    float* __restrict__ C, int M, int N, int K)
{
    __shared__ float As[8][128];
    __shared__ float Bs[8][128];
    const int tid = threadIdx.x;
    const int m0 = blockIdx.y << 7;
    const int n0 = blockIdx.x << 7;
    const int ty = tid >> 4;          // 0..15
    const int tx = tid & 15;          // 0..15

    float acc[8][8];
#pragma unroll
    for (int i = 0; i < 8; i++)
#pragma unroll
        for (int j = 0; j < 8; j++) acc[i][j] = 0.f;

    const int lr = tid >> 1;          // 0..127 (tile row)
    const int lq = (tid & 1) << 2;    // 0 or 4 (k offset)

    for (int kt = 0; kt < K; kt += 8) {
        float4 va = *(const float4*)&A [(size_t)(m0 + lr) * K + kt + lq];
        float4 vb = *(const float4*)&Bw[(size_t)(n0 + lr) * K + kt + lq];
        As[lq + 0][lr] = va.x; As[lq + 1][lr] = va.y;
        As[lq + 2][lr] = va.z; As[lq + 3][lr] = va.w;
        Bs[lq + 0][lr] = vb.x; Bs[lq + 1][lr] = vb.y;
        Bs[lq + 2][lr] = vb.z; Bs[lq + 3][lr] = vb.w;
        __syncthreads();
#pragma unroll
        for (int kk = 0; kk < 8; kk++) {
            float ra[8], rb[8];
            *(float4*)&ra[0] = *(const float4*)&As[kk][ty * 8];
            *(float4*)&ra[4] = *(const float4*)&As[kk][ty * 8 + 4];
            *(float4*)&rb[0] = *(const float4*)&Bs[kk][tx * 8];
            *(float4*)&rb[4] = *(const float4*)&Bs[kk][tx * 8 + 4];
#pragma unroll
            for (int i = 0; i < 8; i++)
#pragma unroll
                for (int j = 0; j < 8; j++)
                    acc[i][j] = fmaf(ra[i], rb[j], acc[i][j]);
        }
        __syncthreads();
    }

    float bb[8];
#pragma unroll
    for (int j = 0; j < 8; j++)
        bb[j] = bias1[n0 + tx * 8 + j] + bias2[n0 + tx * 8 + j];
#pragma unroll
    for (int i = 0; i < 8; i++) {
        float4 o0 = make_float4(acc[i][0] + bb[0], acc[i][1] + bb[1],
                                acc[i][2] + bb[2], acc[i][3] + bb[3]);
        float4 o1 = make_float4(acc[i][4] + bb[4], acc[i][5] + bb[5],
                                acc[i][6] + bb[6], acc[i][7] + bb[7]);
        size_t row = (size_t)(m0 + ty * 8 + i) * N + n0 + tx * 8;
        *(float4*)&C[row]     = o0;
        *(float4*)&C[row + 4] = o1;
    }
}

// ---------------------------------------------------------------------------
// Persistent LSTM scan. 128 CTAs = 16 groups x 8 ranks, 256 threads.
// Group g owns batches [g*4, g*4+4). Rank r owns j in [r*32, r*32+32),
// i.e. gate columns {gate*256 + j}. W_hh slice (128 cols x 256 k = 128KB)
// lives in SMEM for all 512 steps. h exchanged through L2 (double buffer),
// one spin barrier per group per step.
// Dynamic SMEM: Wsh 128KB | hsh 4KB | red 16KB | gsh 2KB = 153600 B.
// ---------------------------------------------------------------------------
__global__ void __launch_bounds__(256) lstm_scan(
    const float* __restrict__ Gx, const float* __restrict__ Whh,
    float* __restrict__ h_all, float* __restrict__ h_last)
{
    extern __shared__ float sm[];
    float* Wsh = sm;                    // [256][128]  (k-major)
    float* hsh = Wsh + 256 * 128;       // [4][256]
    float* red = hsh + 4 * 256;         // [8][512]
    float* gsh = red + 8 * 512;         // [512]

    const int tid = threadIdx.x;
    const int g   = blockIdx.x >> 3;    // group
    const int r   = blockIdx.x & 7;     // rank in group
    const int j0  = r * JPR;
    const int b0  = g * BPG;            // global batch base

    // ---- load W_hh slice into SMEM (k-major for conflict-free LDS.128) ----
    {
        const int c    = tid & 127;             // local col 0..127
        const int half = tid >> 7;              // 0/1
        const int gate = c >> 5, jj = c & 31;
        const int gcol = gate * 256 + j0 + jj;
        const float* wrow = Whh + (size_t)gcol * H_ + half * 128;
#pragma unroll 4
        for (int kk = 0; kk < 128; kk += 4) {
            float4 v = *(const float4*)&wrow[kk];
            int k = half * 128 + kk;
            Wsh[(k + 0) * 128 + c] = v.x;
            Wsh[(k + 1) * 128 + c] = v.y;
            Wsh[(k + 2) * 128 + c] = v.z;
            Wsh[(k + 3) * 128 + c] = v.w;
        }
    }
    for (int i = tid; i < BPG * H_; i += 256) hsh[i] = 0.f;  // h_{-1} = 0
    __syncthreads();

    const int cg = tid & 31;            // column group (4 cols)
    const int kc = tid >> 5;            // k chunk (32 k each)
    float cst = 0.f;                    // cell state (threads < 128)

    // per-thread gx base indices for the two reduce outputs
    size_t gxbase0, gxbase1;
    {
        int o = tid;
        int b = o >> 7, c = o & 127, gate = c >> 5, jj = c & 31;
        gxbase0 = ((size_t)(b0 + b) * T_) * G_ + gate * 256 + j0 + jj;
        o = tid + 256;
        b = o >> 7; c = o & 127; gate = c >> 5; jj = c & 31;
        gxbase1 = ((size_t)(b0 + b) * T_) * G_ + gate * 256 + j0 + jj;
    }

    for (int t = 0; t < T_; t++) {
        // prefetch gates_x for this step (latency hidden under the GEMM)
        float gx0 = __ldg(&Gx[gxbase0 + (size_t)t * G_]);
        float gx1 = __ldg(&Gx[gxbase1 + (size_t)t * G_]);

        // ---- partial GEMM: acc[b][i] over k chunk kc ----
        float acc[4][4];
#pragma unroll
        for (int b = 0; b < 4; b++)
#pragma unroll
            for (int i = 0; i < 4; i++) acc[b][i] = 0.f;

        const float* wk = Wsh + (kc * 32) * 128 + cg * 4;
        const float* hp = hsh + kc * 32;
#pragma unroll 8
        for (int k = 0; k < 32; k++) {
            float4 w = *(const float4*)(wk + k * 128);
            float h0v = hp[k], h1v = hp[256 + k];
            float h2v = hp[512 + k], h3v = hp[768 + k];
            acc[0][0] = fmaf(w.x, h0v, acc[0][0]);
            acc[0][1] = fmaf(w.y, h0v, acc[0][1]);
            acc[0][2] = fmaf(w.z, h0v, acc[0][2]);
            acc[0][3] = fmaf(w.w, h0v, acc[0][3]);
            acc[1][0] = fmaf(w.x, h1v, acc[1][0]);
            acc[1][1] = fmaf(w.y, h1v, acc[1][1]);
            acc[1][2] = fmaf(w.z, h1v, acc[1][2]);
            acc[1][3] = fmaf(w.w, h1v, acc[1][3]);
            acc[2][0] = fmaf(w.x, h2v, acc[2][0]);
            acc[2][1] = fmaf(w.y, h2v, acc[2][1]);
            acc[2][2] = fmaf(w.z, h2v, acc[2][2]);
            acc[2][3] = fmaf(w.w, h2v, acc[2][3]);
            acc[3][0] = fmaf(w.x, h3v, acc[3][0]);
            acc[3][1] = fmaf(w.y, h3v, acc[3][1]);
            acc[3][2] = fmaf(w.z, h3v, acc[3][2]);
            acc[3][3] = fmaf(w.w, h3v, acc[3][3]);
        }
#pragma unroll
        for (int b = 0; b < 4; b++)
#pragma unroll
            for (int i = 0; i < 4; i++)
                red[kc * 512 + b * 128 + cg * 4 + i] = acc[b][i];
        __syncthreads();

        // ---- reduce over 8 k-chunks, add gates_x ----
        {
            float s0 = 0.f, s1 = 0.f;
#pragma unroll
            for (int p = 0; p < 8; p++) {
                s0 += red[p * 512 + tid];
                s1 += red[p * 512 + tid + 256];
            }
            gsh[tid]       = s0 + gx0;
            gsh[tid + 256] = s1 + gx1;
        }
        __syncthreads();

        // ---- activations + state update (threads 0..127: one (b, jj)) ----
        if (tid < 128) {
            const int b = tid >> 5, jj = tid & 31;
            float iv = gsh[b * 128 + jj];
            float fv = gsh[b * 128 + 32 + jj];
            float gv = gsh[b * 128 + 64 + jj];
            float ov = gsh[b * 128 + 96 + jj];
            iv = 1.f / (1.f + expf(-iv));
            fv = 1.f / (1.f + expf(-fv));
            gv = tanhf(gv);
            ov = 1.f / (1.f + expf(-ov));
            cst = fv * cst + iv * gv;
            float hv = ov * tanhf(cst);

            const int gb = b0 + b, j = j0 + jj;
            d_hx[t & 1][gb * H_ + j] = hv;
            if (h_all)  h_all[((size_t)gb * T_ + t) * H_ + j] = hv;
            if (h_last && t == T_ - 1) h_last[gb * H_ + j] = hv;
        }
        __syncthreads();
        if (t == T_ - 1) break;

        // ---- group barrier (all CTAs resident: 128 blocks <= 148 SMs) ----
        if (tid == 0) {
            __threadfence();                       // publish h writes
            atomicAdd(&d_bar[g], 1);
            const int target = RPG * (t + 1);
            while (atomicAdd(&d_bar[g], 0) < target) { }
            __threadfence();                       // acquire peers' writes
        }
        __syncthreads();

        // ---- reload full group h (4KB) bypassing caches ----
        {
            const float* src = &d_hx[t & 1][b0 * H_];
            for (int i = tid; i < BPG * H_; i += 256)
                hsh[i] = __ldcv(&src[i]);
        }
        __syncthreads();
    }

    // ---- reset barrier counters so every graph replay starts clean ----
    __syncthreads();
    if (tid == 0) {
        __threadfence();
        atomicAdd(&d_done[g], 1);
        if (r == 0) {
            while (atomicAdd(&d_done[g], 0) < RPG) { }
            d_bar[g]  = 0;
            d_done[g] = 0;
            __threadfence();
        }
    }
}

// ---------------------------------------------------------------------------
// Head: logits = h_last @ fc_w^T + fc_b ; softmax rows. One block.
// ---------------------------------------------------------------------------
__global__ void __launch_bounds__(192) head_kernel(
    const float* __restrict__ hl, const float* __restrict__ fw,
    const float* __restrict__ fb, float* __restrict__ out)
{
    __shared__ float lg[B_ * C_];
    const int tid = threadIdx.x;
    if (tid < B_ * C_) {
        const int b = tid / C_, c = tid % C_;
        float s = fb[c];
        const float* hr = hl + b * H_;
        const float* wr = fw + c * H_;
#pragma unroll 8
        for (int j = 0; j < H_; j++) s = fmaf(hr[j], wr[j], s);
        lg[tid] = s;
    }
    __syncthreads();
    if (tid < B_) {
        float a = lg[tid * 3], b2 = lg[tid * 3 + 1], c2 = lg[tid * 3 + 2];
        float m = fmaxf(a, fmaxf(b2, c2));
        float e0 = expf(a - m), e1 = expf(b2 - m), e2 = expf(c2 - m);
        float inv = 1.f / (e0 + e1 + e2);
        out[tid * 3]     = e0 * inv;
        out[tid * 3 + 1] = e1 * inv;
        out[tid * 3 + 2] = e2 * inv;
    }
}

// ---------------------------------------------------------------------------
extern "C" void kernel_launch(void* const* d_in, const int* in_sizes, int n_in,
                              void* d_out, int out_size)
{
    const float* x    = (const float*)d_in[0];
    const float* Wih0 = (const float*)d_in[1];
    const float* Whh0 = (const float*)d_in[2];
    const float* bih0 = (const float*)d_in[3];
    const float* bhh0 = (const float*)d_in[4];
    const float* Wih1 = (const float*)d_in[5];
    const float* Whh1 = (const float*)d_in[6];
    const float* bih1 = (const float*)d_in[7];
    const float* bhh1 = (const float*)d_in[8];
    const float* fw   = (const float*)d_in[9];
    const float* fb   = (const float*)d_in[10];
    float* out = (float*)d_out;

    float *G0, *G1, *H0, *HL;
    cudaGetSymbolAddress((void**)&G0, d_G0);
    cudaGetSymbolAddress((void**)&G1, d_G1);
    cudaGetSymbolAddress((void**)&H0, d_H0);
    cudaGetSymbolAddress((void**)&HL, d_HL);

    const int SCAN_SMEM = (256 * 128 + 4 * 256 + 8 * 512 + 512) * 4; // 153600
    cudaFuncSetAttribute(lstm_scan, cudaFuncAttributeMaxDynamicSharedMemorySize,
                         SCAN_SMEM);

    const int M = B_ * T_;
    dim3 ggrid(G_ / 128, M / 128);

    // layer 0: gates_x0 = x @ W_ih_0^T + b
    gemm_nt_bias<<<ggrid, 256>>>(x, Wih0, bih0, bhh0, G0, M, G_, I_);
    // layer 0 recurrence -> full h0
    lstm_scan<<<NGROUP * RPG, 256, SCAN_SMEM>>>(G0, Whh0, H0, nullptr);
    // layer 1: gates_x1 = h0 @ W_ih_1^T + b
    gemm_nt_bias<<<ggrid, 256>>>(H0, Wih1, bih1, bhh1, G1, M, G_, H_);
    // layer 1 recurrence -> last h only
    lstm_scan<<<NGROUP * RPG, 256, SCAN_SMEM>>>(G1, Whh1, nullptr, HL);
    // FC + softmax
    head_kernel<<<1, 192>>>(HL, fw, fb, out);
}

// round 5
// speedup vs baseline: 1.4843x; 1.4843x over previous
#include <cuda_runtime.h>
#include <math.h>

#define B_ 64
#define T_ 512
#define I_ 128
#define H_ 256
#define G_ 1024   // 4*H
#define C_ 3

#define NGROUP 16   // batch groups
#define BPG 4       // batches per group
#define RPG 8       // CTAs per group
#define JPR 32      // j-values per CTA (H / RPG)

// ---------------- scratch (device globals; no allocation allowed) ----------
__device__ float d_G0[B_ * T_ * G_];     // gates_x layer 0   (134 MB)
__device__ float d_G1[B_ * T_ * G_];     // gates_x layer 1   (134 MB)
__device__ float d_H0[B_ * T_ * H_];     // h outputs layer 0 (33.5 MB)
__device__ float d_HL[B_ * H_];          // last h of layer 1
__device__ float d_hx[2][B_ * H_];       // h exchange, double buffered
__device__ int   d_bar[NGROUP];          // per-group step barrier (zero-init)
__device__ int   d_done[NGROUP];         // per-group exit counter (zero-init)

// ---------------------------------------------------------------------------
// GEMM (NT): C[m][n] = sum_k A[m*K+k] * Bw[n*K+k] + bias1[n] + bias2[n]
// BM=BN=128, BK=8, 256 threads, 8x8 per thread. M,N,K all divisible.
// ---------------------------------------------------------------------------
__global__ void __launch_bounds__(256) gemm_nt_bias(
    const float* __restrict__ A, const float* __restrict__ Bw,
    const float* __restrict__ bias1, const float* __restrict__ bias2,
    float* __restrict__ C, int M, int N, int K)
{
    __shared__ float As[8][128];
    __shared__ float Bs[8][128];
    const int tid = threadIdx.x;
    const int m0 = blockIdx.y << 7;
    const int n0 = blockIdx.x << 7;
    const int ty = tid >> 4;          // 0..15
    const int tx = tid & 15;          // 0..15

    float acc[8][8];
#pragma unroll
    for (int i = 0; i < 8; i++)
#pragma unroll
        for (int j = 0; j < 8; j++) acc[i][j] = 0.f;

    const int lr = tid >> 1;          // 0..127 (tile row)
    const int lq = (tid & 1) << 2;    // 0 or 4 (k offset)

    for (int kt = 0; kt < K; kt += 8) {
        float4 va = *(const float4*)&A [(size_t)(m0 + lr) * K + kt + lq];
        float4 vb = *(const float4*)&Bw[(size_t)(n0 + lr) * K + kt + lq];
        As[lq + 0][lr] = va.x; As[lq + 1][lr] = va.y;
        As[lq + 2][lr] = va.z; As[lq + 3][lr] = va.w;
        Bs[lq + 0][lr] = vb.x; Bs[lq + 1][lr] = vb.y;
        Bs[lq + 2][lr] = vb.z; Bs[lq + 3][lr] = vb.w;
        __syncthreads();
#pragma unroll
        for (int kk = 0; kk < 8; kk++) {
            float ra[8], rb[8];
            *(float4*)&ra[0] = *(const float4*)&As[kk][ty * 8];
            *(float4*)&ra[4] = *(const float4*)&As[kk][ty * 8 + 4];
            *(float4*)&rb[0] = *(const float4*)&Bs[kk][tx * 8];
            *(float4*)&rb[4] = *(const float4*)&Bs[kk][tx * 8 + 4];
#pragma unroll
            for (int i = 0; i < 8; i++)
#pragma unroll
                for (int j = 0; j < 8; j++)
                    acc[i][j] = fmaf(ra[i], rb[j], acc[i][j]);
        }
        __syncthreads();
    }

    float bb[8];
#pragma unroll
    for (int j = 0; j < 8; j++)
        bb[j] = bias1[n0 + tx * 8 + j] + bias2[n0 + tx * 8 + j];
#pragma unroll
    for (int i = 0; i < 8; i++) {
        float4 o0 = make_float4(acc[i][0] + bb[0], acc[i][1] + bb[1],
                                acc[i][2] + bb[2], acc[i][3] + bb[3]);
        float4 o1 = make_float4(acc[i][4] + bb[4], acc[i][5] + bb[5],
                                acc[i][6] + bb[6], acc[i][7] + bb[7]);
        size_t row = (size_t)(m0 + ty * 8 + i) * N + n0 + tx * 8;
        *(float4*)&C[row]     = o0;
        *(float4*)&C[row + 4] = o1;
    }
}

// ---------------------------------------------------------------------------
// Persistent LSTM scan. 128 CTAs = 16 groups x 8 ranks, 256 threads.
// Group g owns batches [g*4, g*4+4). Rank r owns j in [r*32, r*32+32),
// i.e. gate columns {gate*256 + j}. W_hh slice (128 cols x 256 k = 128KB)
// lives in SMEM for all 512 steps. h exchanged through L2 (double buffer),
// one spin barrier per group per step.
// Dynamic SMEM: Wsh 128KB | hsh 4KB | red 16KB | gsh 2KB = 153600 B.
// ---------------------------------------------------------------------------
__global__ void __launch_bounds__(256) lstm_scan(
    const float* __restrict__ Gx, const float* __restrict__ Whh,
    float* __restrict__ h_all, float* __restrict__ h_last)
{
    extern __shared__ float sm[];
    float* Wsh = sm;                    // [256][128]  (k-major)
    float* hsh = Wsh + 256 * 128;       // [4][256]
    float* red = hsh + 4 * 256;         // [8][512]
    float* gsh = red + 8 * 512;         // [512]

    const int tid = threadIdx.x;
    const int g   = blockIdx.x >> 3;    // group
    const int r   = blockIdx.x & 7;     // rank in group
    const int j0  = r * JPR;
    const int b0  = g * BPG;            // global batch base

    // ---- load W_hh slice into SMEM (k-major for conflict-free LDS.128) ----
    {
        const int c    = tid & 127;             // local col 0..127
        const int half = tid >> 7;              // 0/1
        const int gate = c >> 5, jj = c & 31;
        const int gcol = gate * 256 + j0 + jj;
        const float* wrow = Whh + (size_t)gcol * H_ + half * 128;
#pragma unroll 4
        for (int kk = 0; kk < 128; kk += 4) {
            float4 v = *(const float4*)&wrow[kk];
            int k = half * 128 + kk;
            Wsh[(k + 0) * 128 + c] = v.x;
            Wsh[(k + 1) * 128 + c] = v.y;
            Wsh[(k + 2) * 128 + c] = v.z;
            Wsh[(k + 3) * 128 + c] = v.w;
        }
    }
    for (int i = tid; i < BPG * H_; i += 256) hsh[i] = 0.f;  // h_{-1} = 0
    __syncthreads();

    const int cg = tid & 31;            // column group (4 cols)
    const int kc = tid >> 5;            // k chunk (32 k each)
    float cst = 0.f;                    // cell state (threads < 128)

    // per-thread gx base indices for the two reduce outputs
    size_t gxbase0, gxbase1;
    {
        int o = tid;
        int b = o >> 7, c = o & 127, gate = c >> 5, jj = c & 31;
        gxbase0 = ((size_t)(b0 + b) * T_) * G_ + gate * 256 + j0 + jj;
        o = tid + 256;
        b = o >> 7; c = o & 127; gate = c >> 5; jj = c & 31;
        gxbase1 = ((size_t)(b0 + b) * T_) * G_ + gate * 256 + j0 + jj;
    }

    for (int t = 0; t < T_; t++) {
        // prefetch gates_x for this step (latency hidden under the GEMM)
        float gx0 = __ldg(&Gx[gxbase0 + (size_t)t * G_]);
        float gx1 = __ldg(&Gx[gxbase1 + (size_t)t * G_]);

        // ---- partial GEMM: acc[b][i] over k chunk kc ----
        float acc[4][4];
#pragma unroll
        for (int b = 0; b < 4; b++)
#pragma unroll
            for (int i = 0; i < 4; i++) acc[b][i] = 0.f;

        const float* wk = Wsh + (kc * 32) * 128 + cg * 4;
        const float* hp = hsh + kc * 32;
#pragma unroll 8
        for (int k = 0; k < 32; k++) {
            float4 w = *(const float4*)(wk + k * 128);
            float h0v = hp[k], h1v = hp[256 + k];
            float h2v = hp[512 + k], h3v = hp[768 + k];
            acc[0][0] = fmaf(w.x, h0v, acc[0][0]);
            acc[0][1] = fmaf(w.y, h0v, acc[0][1]);
            acc[0][2] = fmaf(w.z, h0v, acc[0][2]);
            acc[0][3] = fmaf(w.w, h0v, acc[0][3]);
            acc[1][0] = fmaf(w.x, h1v, acc[1][0]);
            acc[1][1] = fmaf(w.y, h1v, acc[1][1]);
            acc[1][2] = fmaf(w.z, h1v, acc[1][2]);
            acc[1][3] = fmaf(w.w, h1v, acc[1][3]);
            acc[2][0] = fmaf(w.x, h2v, acc[2][0]);
            acc[2][1] = fmaf(w.y, h2v, acc[2][1]);
            acc[2][2] = fmaf(w.z, h2v, acc[2][2]);
            acc[2][3] = fmaf(w.w, h2v, acc[2][3]);
            acc[3][0] = fmaf(w.x, h3v, acc[3][0]);
            acc[3][1] = fmaf(w.y, h3v, acc[3][1]);
            acc[3][2] = fmaf(w.z, h3v, acc[3][2]);
            acc[3][3] = fmaf(w.w, h3v, acc[3][3]);
        }
#pragma unroll
        for (int b = 0; b < 4; b++)
#pragma unroll
            for (int i = 0; i < 4; i++)
                red[kc * 512 + b * 128 + cg * 4 + i] = acc[b][i];
        __syncthreads();

        // ---- reduce over 8 k-chunks, add gates_x ----
        {
            float s0 = 0.f, s1 = 0.f;
#pragma unroll
            for (int p = 0; p < 8; p++) {
                s0 += red[p * 512 + tid];
                s1 += red[p * 512 + tid + 256];
            }
            gsh[tid]       = s0 + gx0;
            gsh[tid + 256] = s1 + gx1;
        }
        __syncthreads();

        // ---- activations + state update (threads 0..127: one (b, jj)) ----
        if (tid < 128) {
            const int b = tid >> 5, jj = tid & 31;
            float iv = gsh[b * 128 + jj];
            float fv = gsh[b * 128 + 32 + jj];
            float gv = gsh[b * 128 + 64 + jj];
            float ov = gsh[b * 128 + 96 + jj];
            iv = 1.f / (1.f + expf(-iv));
            fv = 1.f / (1.f + expf(-fv));
            gv = tanhf(gv);
            ov = 1.f / (1.f + expf(-ov));
            cst = fv * cst + iv * gv;
            float hv = ov * tanhf(cst);

            const int gb = b0 + b, j = j0 + jj;
            d_hx[t & 1][gb * H_ + j] = hv;
            if (h_all)  h_all[((size_t)gb * T_ + t) * H_ + j] = hv;
            if (h_last && t == T_ - 1) h_last[gb * H_ + j] = hv;
        }
        __syncthreads();
        if (t == T_ - 1) break;

        // ---- group barrier (all CTAs resident: 128 blocks <= 148 SMs) ----
        if (tid == 0) {
            __threadfence();                       // publish h writes
            atomicAdd(&d_bar[g], 1);
            const int target = RPG * (t + 1);
            while (atomicAdd(&d_bar[g], 0) < target) { }
            __threadfence();                       // acquire peers' writes
        }
        __syncthreads();

        // ---- reload full group h (4KB) bypassing caches ----
        {
            const float* src = &d_hx[t & 1][b0 * H_];
            for (int i = tid; i < BPG * H_; i += 256)
                hsh[i] = __ldcv(&src[i]);
        }
        __syncthreads();
    }

    // ---- reset barrier counters so every graph replay starts clean ----
    __syncthreads();
    if (tid == 0) {
        __threadfence();
        atomicAdd(&d_done[g], 1);
        if (r == 0) {
            while (atomicAdd(&d_done[g], 0) < RPG) { }
            d_bar[g]  = 0;
            d_done[g] = 0;
            __threadfence();
        }
    }
}

// ---------------------------------------------------------------------------
// Head: logits = h_last @ fc_w^T + fc_b ; softmax rows. One block.
// ---------------------------------------------------------------------------
__global__ void __launch_bounds__(192) head_kernel(
    const float* __restrict__ hl, const float* __restrict__ fw,
    const float* __restrict__ fb, float* __restrict__ out)
{
    __shared__ float lg[B_ * C_];
    const int tid = threadIdx.x;
    if (tid < B_ * C_) {
        const int b = tid / C_, c = tid % C_;
        float s = fb[c];
        const float* hr = hl + b * H_;
        const float* wr = fw + c * H_;
#pragma unroll 8
        for (int j = 0; j < H_; j++) s = fmaf(hr[j], wr[j], s);
        lg[tid] = s;
    }
    __syncthreads();
    if (tid < B_) {
        float a = lg[tid * 3], b2 = lg[tid * 3 + 1], c2 = lg[tid * 3 + 2];
        float m = fmaxf(a, fmaxf(b2, c2));
        float e0 = expf(a - m), e1 = expf(b2 - m), e2 = expf(c2 - m);
        float inv = 1.f / (e0 + e1 + e2);
        out[tid * 3]     = e0 * inv;
        out[tid * 3 + 1] = e1 * inv;
        out[tid * 3 + 2] = e2 * inv;
    }
}

// ---------------------------------------------------------------------------
extern "C" void kernel_launch(void* const* d_in, const int* in_sizes, int n_in,
                              void* d_out, int out_size)
{
    const float* x    = (const float*)d_in[0];
    const float* Wih0 = (const float*)d_in[1];
    const float* Whh0 = (const float*)d_in[2];
    const float* bih0 = (const float*)d_in[3];
    const float* bhh0 = (const float*)d_in[4];
    const float* Wih1 = (const float*)d_in[5];
    const float* Whh1 = (const float*)d_in[6];
    const float* bih1 = (const float*)d_in[7];
    const float* bhh1 = (const float*)d_in[8];
    const float* fw   = (const float*)d_in[9];
    const float* fb   = (const float*)d_in[10];
    float* out = (float*)d_out;

    float *G0, *G1, *H0, *HL;
    cudaGetSymbolAddress((void**)&G0, d_G0);
    cudaGetSymbolAddress((void**)&G1, d_G1);
    cudaGetSymbolAddress((void**)&H0, d_H0);
    cudaGetSymbolAddress((void**)&HL, d_HL);

    const int SCAN_SMEM = (256 * 128 + 4 * 256 + 8 * 512 + 512) * 4; // 153600
    cudaFuncSetAttribute(lstm_scan, cudaFuncAttributeMaxDynamicSharedMemorySize,
                         SCAN_SMEM);

    const int M = B_ * T_;
    dim3 ggrid(G_ / 128, M / 128);

    // layer 0: gates_x0 = x @ W_ih_0^T + b
    gemm_nt_bias<<<ggrid, 256>>>(x, Wih0, bih0, bhh0, G0, M, G_, I_);
    // layer 0 recurrence -> full h0
    lstm_scan<<<NGROUP * RPG, 256, SCAN_SMEM>>>(G0, Whh0, H0, nullptr);
    // layer 1: gates_x1 = h0 @ W_ih_1^T + b
    gemm_nt_bias<<<ggrid, 256>>>(H0, Wih1, bih1, bhh1, G1, M, G_, H_);
    // layer 1 recurrence -> last h only
    lstm_scan<<<NGROUP * RPG, 256, SCAN_SMEM>>>(G1, Whh1, nullptr, HL);
    // FC + softmax
    head_kernel<<<1, 192>>>(HL, fw, fb, out);
}

// round 6
// speedup vs baseline: 1.4859x; 1.0011x over previous
#include <cuda_runtime.h>
#include <math.h>

#define B_ 64
#define T_ 512
#define I_ 128
#define H_ 256
#define G_ 1024   // 4*H
#define C_ 3

#define NGROUP 16   // batch groups
#define BPG 4       // batches per group
#define RPG 8       // CTAs per group
#define JPR 32      // j-values per CTA (H / RPG)

// ---------------- scratch (device globals; no allocation allowed) ----------
__device__ float d_G0[B_ * T_ * G_];     // gates_x layer 0   (134 MB)
__device__ float d_G1[B_ * T_ * G_];     // gates_x layer 1   (134 MB)
__device__ float d_H0[B_ * T_ * H_];     // h outputs layer 0 (33.5 MB)
__device__ float d_HL[B_ * H_];          // last h of layer 1
__device__ float d_hx[2][B_ * H_];       // h exchange, double buffered
__device__ int   d_bar[NGROUP];          // per-group step barrier (zero-init)
__device__ int   d_done[NGROUP];         // per-group exit counter (zero-init)

// ---------------------------------------------------------------------------
// GEMM (NT): C[m][n] = sum_k A[m*K+k] * Bw[n*K+k] + bias1[n] + bias2[n]
// BM=BN=128, BK=8, 256 threads, 8x8 per thread. M,N,K all divisible.
// ---------------------------------------------------------------------------
__global__ void __launch_bounds__(256) gemm_nt_bias(
    const float* __restrict__ A, const float* __restrict__ Bw,
    const float* __restrict__ bias1, const float* __restrict__ bias2,
    float* __restrict__ C, int M, int N, int K)
{
    __shared__ float As[8][128];
    __shared__ float Bs[8][128];
    const int tid = threadIdx.x;
    const int m0 = blockIdx.y << 7;
    const int n0 = blockIdx.x << 7;
    const int ty = tid >> 4;          // 0..15
    const int tx = tid & 15;          // 0..15

    float acc[8][8];
#pragma unroll
    for (int i = 0; i < 8; i++)
#pragma unroll
        for (int j = 0; j < 8; j++) acc[i][j] = 0.f;

    const int lr = tid >> 1;          // 0..127 (tile row)
    const int lq = (tid & 1) << 2;    // 0 or 4 (k offset)

    for (int kt = 0; kt < K; kt += 8) {
        float4 va = *(const float4*)&A [(size_t)(m0 + lr) * K + kt + lq];
        float4 vb = *(const float4*)&Bw[(size_t)(n0 + lr) * K + kt + lq];
        As[lq + 0][lr] = va.x; As[lq + 1][lr] = va.y;
        As[lq + 2][lr] = va.z; As[lq + 3][lr] = va.w;
        Bs[lq + 0][lr] = vb.x; Bs[lq + 1][lr] = vb.y;
        Bs[lq + 2][lr] = vb.z; Bs[lq + 3][lr] = vb.w;
        __syncthreads();
#pragma unroll
        for (int kk = 0; kk < 8; kk++) {
            float ra[8], rb[8];
            *(float4*)&ra[0] = *(const float4*)&As[kk][ty * 8];
            *(float4*)&ra[4] = *(const float4*)&As[kk][ty * 8 + 4];
            *(float4*)&rb[0] = *(const float4*)&Bs[kk][tx * 8];
            *(float4*)&rb[4] = *(const float4*)&Bs[kk][tx * 8 + 4];
#pragma unroll
            for (int i = 0; i < 8; i++)
#pragma unroll
                for (int j = 0; j < 8; j++)
                    acc[i][j] = fmaf(ra[i], rb[j], acc[i][j]);
        }
        __syncthreads();
    }

    float bb[8];
#pragma unroll
    for (int j = 0; j < 8; j++)
        bb[j] = bias1[n0 + tx * 8 + j] + bias2[n0 + tx * 8 + j];
#pragma unroll
    for (int i = 0; i < 8; i++) {
        float4 o0 = make_float4(acc[i][0] + bb[0], acc[i][1] + bb[1],
                                acc[i][2] + bb[2], acc[i][3] + bb[3]);
        float4 o1 = make_float4(acc[i][4] + bb[4], acc[i][5] + bb[5],
                                acc[i][6] + bb[6], acc[i][7] + bb[7]);
        size_t row = (size_t)(m0 + ty * 8 + i) * N + n0 + tx * 8;
        *(float4*)&C[row]     = o0;
        *(float4*)&C[row + 4] = o1;
    }
}

// ---------------------------------------------------------------------------
// Persistent LSTM scan. 128 CTAs = 16 groups x 8 ranks, 256 threads.
// Group g owns batches [g*4, g*4+4). Rank r owns j in [r*32, r*32+32),
// i.e. gate columns {gate*256 + j}. W_hh slice (128 cols x 256 k = 128KB)
// lives in SMEM for all 512 steps. h exchanged through L2 (double buffer),
// one spin barrier per group per step.
// Dynamic SMEM: Wsh 128KB | hsh 4KB | red 16KB | gsh 2KB = 153600 B.
// ---------------------------------------------------------------------------
__global__ void __launch_bounds__(256) lstm_scan(
    const float* __restrict__ Gx, const float* __restrict__ Whh,
    float* __restrict__ h_all, float* __restrict__ h_last)
{
    extern __shared__ float sm[];
    float* Wsh = sm;                    // [256][128]  (k-major)
    float* hsh = Wsh + 256 * 128;       // [4][256]
    float* red = hsh + 4 * 256;         // [8][512]
    float* gsh = red + 8 * 512;         // [512]

    const int tid = threadIdx.x;
    const int g   = blockIdx.x >> 3;    // group
    const int r   = blockIdx.x & 7;     // rank in group
    const int j0  = r * JPR;
    const int b0  = g * BPG;            // global batch base

    // ---- load W_hh slice into SMEM (k-major for conflict-free LDS.128) ----
    {
        const int c    = tid & 127;             // local col 0..127
        const int half = tid >> 7;              // 0/1
        const int gate = c >> 5, jj = c & 31;
        const int gcol = gate * 256 + j0 + jj;
        const float* wrow = Whh + (size_t)gcol * H_ + half * 128;
#pragma unroll 4
        for (int kk = 0; kk < 128; kk += 4) {
            float4 v = *(const float4*)&wrow[kk];
            int k = half * 128 + kk;
            Wsh[(k + 0) * 128 + c] = v.x;
            Wsh[(k + 1) * 128 + c] = v.y;
            Wsh[(k + 2) * 128 + c] = v.z;
            Wsh[(k + 3) * 128 + c] = v.w;
        }
    }
    for (int i = tid; i < BPG * H_; i += 256) hsh[i] = 0.f;  // h_{-1} = 0
    __syncthreads();

    const int cg = tid & 31;            // column group (4 cols)
    const int kc = tid >> 5;            // k chunk (32 k each)
    float cst = 0.f;                    // cell state (threads < 128)

    // per-thread gx base indices for the two reduce outputs
    size_t gxbase0, gxbase1;
    {
        int o = tid;
        int b = o >> 7, c = o & 127, gate = c >> 5, jj = c & 31;
        gxbase0 = ((size_t)(b0 + b) * T_) * G_ + gate * 256 + j0 + jj;
        o = tid + 256;
        b = o >> 7; c = o & 127; gate = c >> 5; jj = c & 31;
        gxbase1 = ((size_t)(b0 + b) * T_) * G_ + gate * 256 + j0 + jj;
    }

    for (int t = 0; t < T_; t++) {
        // prefetch gates_x for this step (latency hidden under the GEMM)
        float gx0 = __ldg(&Gx[gxbase0 + (size_t)t * G_]);
        float gx1 = __ldg(&Gx[gxbase1 + (size_t)t * G_]);

        // ---- partial GEMM: acc[b][i] over k chunk kc ----
        float acc[4][4];
#pragma unroll
        for (int b = 0; b < 4; b++)
#pragma unroll
            for (int i = 0; i < 4; i++) acc[b][i] = 0.f;

        const float* wk = Wsh + (kc * 32) * 128 + cg * 4;
        const float* hp = hsh + kc * 32;
#pragma unroll 8
        for (int k = 0; k < 32; k++) {
            float4 w = *(const float4*)(wk + k * 128);
            float h0v = hp[k], h1v = hp[256 + k];
            float h2v = hp[512 + k], h3v = hp[768 + k];
            acc[0][0] = fmaf(w.x, h0v, acc[0][0]);
            acc[0][1] = fmaf(w.y, h0v, acc[0][1]);
            acc[0][2] = fmaf(w.z, h0v, acc[0][2]);
            acc[0][3] = fmaf(w.w, h0v, acc[0][3]);
            acc[1][0] = fmaf(w.x, h1v, acc[1][0]);
            acc[1][1] = fmaf(w.y, h1v, acc[1][1]);
            acc[1][2] = fmaf(w.z, h1v, acc[1][2]);
            acc[1][3] = fmaf(w.w, h1v, acc[1][3]);
            acc[2][0] = fmaf(w.x, h2v, acc[2][0]);
            acc[2][1] = fmaf(w.y, h2v, acc[2][1]);
            acc[2][2] = fmaf(w.z, h2v, acc[2][2]);
            acc[2][3] = fmaf(w.w, h2v, acc[2][3]);
            acc[3][0] = fmaf(w.x, h3v, acc[3][0]);
            acc[3][1] = fmaf(w.y, h3v, acc[3][1]);
            acc[3][2] = fmaf(w.z, h3v, acc[3][2]);
            acc[3][3] = fmaf(w.w, h3v, acc[3][3]);
        }
#pragma unroll
        for (int b = 0; b < 4; b++)
#pragma unroll
            for (int i = 0; i < 4; i++)
                red[kc * 512 + b * 128 + cg * 4 + i] = acc[b][i];
        __syncthreads();

        // ---- reduce over 8 k-chunks, add gates_x ----
        {
            float s0 = 0.f, s1 = 0.f;
#pragma unroll
            for (int p = 0; p < 8; p++) {
                s0 += red[p * 512 + tid];
                s1 += red[p * 512 + tid + 256];
            }
            gsh[tid]       = s0 + gx0;
            gsh[tid + 256] = s1 + gx1;
        }
        __syncthreads();

        // ---- activations + state update (threads 0..127: one (b, jj)) ----
        if (tid < 128) {
            const int b = tid >> 5, jj = tid & 31;
            float iv = gsh[b * 128 + jj];
            float fv = gsh[b * 128 + 32 + jj];
            float gv = gsh[b * 128 + 64 + jj];
            float ov = gsh[b * 128 + 96 + jj];
            iv = 1.f / (1.f + expf(-iv));
            fv = 1.f / (1.f + expf(-fv));
            gv = tanhf(gv);
            ov = 1.f / (1.f + expf(-ov));
            cst = fv * cst + iv * gv;
            float hv = ov * tanhf(cst);

            const int gb = b0 + b, j = j0 + jj;
            d_hx[t & 1][gb * H_ + j] = hv;
            if (h_all)  h_all[((size_t)gb * T_ + t) * H_ + j] = hv;
            if (h_last && t == T_ - 1) h_last[gb * H_ + j] = hv;
        }
        __syncthreads();
        if (t == T_ - 1) break;

        // ---- group barrier (all CTAs resident: 128 blocks <= 148 SMs) ----
        if (tid == 0) {
            __threadfence();                       // publish h writes
            atomicAdd(&d_bar[g], 1);
            const int target = RPG * (t + 1);
            while (atomicAdd(&d_bar[g], 0) < target) { }
            __threadfence();                       // acquire peers' writes
        }
        __syncthreads();

        // ---- reload full group h (4KB) bypassing caches ----
        {
            const float* src = &d_hx[t & 1][b0 * H_];
            for (int i = tid; i < BPG * H_; i += 256)
                hsh[i] = __ldcv(&src[i]);
        }
        __syncthreads();
    }

    // ---- reset barrier counters so every graph replay starts clean ----
    __syncthreads();
    if (tid == 0) {
        __threadfence();
        atomicAdd(&d_done[g], 1);
        if (r == 0) {
            while (atomicAdd(&d_done[g], 0) < RPG) { }
            d_bar[g]  = 0;
            d_done[g] = 0;
            __threadfence();
        }
    }
}

// ---------------------------------------------------------------------------
// Head: logits = h_last @ fc_w^T + fc_b ; softmax rows. One block.
// ---------------------------------------------------------------------------
__global__ void __launch_bounds__(192) head_kernel(
    const float* __restrict__ hl, const float* __restrict__ fw,
    const float* __restrict__ fb, float* __restrict__ out)
{
    __shared__ float lg[B_ * C_];
    const int tid = threadIdx.x;
    if (tid < B_ * C_) {
        const int b = tid / C_, c = tid % C_;
        float s = fb[c];
        const float* hr = hl + b * H_;
        const float* wr = fw + c * H_;
#pragma unroll 8
        for (int j = 0; j < H_; j++) s = fmaf(hr[j], wr[j], s);
        lg[tid] = s;
    }
    __syncthreads();
    if (tid < B_) {
        float a = lg[tid * 3], b2 = lg[tid * 3 + 1], c2 = lg[tid * 3 + 2];
        float m = fmaxf(a, fmaxf(b2, c2));
        float e0 = expf(a - m), e1 = expf(b2 - m), e2 = expf(c2 - m);
        float inv = 1.f / (e0 + e1 + e2);
        out[tid * 3]     = e0 * inv;
        out[tid * 3 + 1] = e1 * inv;
        out[tid * 3 + 2] = e2 * inv;
    }
}

// ---------------------------------------------------------------------------
extern "C" void kernel_launch(void* const* d_in, const int* in_sizes, int n_in,
                              void* d_out, int out_size)
{
    const float* x    = (const float*)d_in[0];
    const float* Wih0 = (const float*)d_in[1];
    const float* Whh0 = (const float*)d_in[2];
    const float* bih0 = (const float*)d_in[3];
    const float* bhh0 = (const float*)d_in[4];
    const float* Wih1 = (const float*)d_in[5];
    const float* Whh1 = (const float*)d_in[6];
    const float* bih1 = (const float*)d_in[7];
    const float* bhh1 = (const float*)d_in[8];
    const float* fw   = (const float*)d_in[9];
    const float* fb   = (const float*)d_in[10];
    float* out = (float*)d_out;

    float *G0, *G1, *H0, *HL;
    cudaGetSymbolAddress((void**)&G0, d_G0);
    cudaGetSymbolAddress((void**)&G1, d_G1);
    cudaGetSymbolAddress((void**)&H0, d_H0);
    cudaGetSymbolAddress((void**)&HL, d_HL);

    const int SCAN_SMEM = (256 * 128 + 4 * 256 + 8 * 512 + 512) * 4; // 153600
    cudaFuncSetAttribute(lstm_scan, cudaFuncAttributeMaxDynamicSharedMemorySize,
                         SCAN_SMEM);

    const int M = B_ * T_;
    dim3 ggrid(G_ / 128, M / 128);

    // layer 0: gates_x0 = x @ W_ih_0^T + b
    gemm_nt_bias<<<ggrid, 256>>>(x, Wih0, bih0, bhh0, G0, M, G_, I_);
    // layer 0 recurrence -> full h0
    lstm_scan<<<NGROUP * RPG, 256, SCAN_SMEM>>>(G0, Whh0, H0, nullptr);
    // layer 1: gates_x1 = h0 @ W_ih_1^T + b
    gemm_nt_bias<<<ggrid, 256>>>(H0, Wih1, bih1, bhh1, G1, M, G_, H_);
    // layer 1 recurrence -> last h only
    lstm_scan<<<NGROUP * RPG, 256, SCAN_SMEM>>>(G1, Whh1, nullptr, HL);
    // FC + softmax
    head_kernel<<<1, 192>>>(HL, fw, fb, out);
}